// round 1
// baseline (speedup 1.0000x reference)
#include <cuda_runtime.h>
#include <math.h>

#define NB 8
#define C 96
#define G 4
#define CG 24
#define HH 56
#define HW 3136
#define P 25088            // NB*HW
#define HD 384
#define NCHW (NB*C*HW)     // 2408448
#define EPSF 1e-12f

// ---------------- device scratch (no allocations allowed) ----------------
__device__ float g_xnn[NCHW];     // relu(LN1(x)) channel-normalized
__device__ float g_h[NCHW];       // NNMF h (unnormalized; normalized on read)
__device__ float g_t[NCHW];       // ratio buffer, later x2 = x + attn
__device__ float g_lncf[NCHW];    // LN2 output, [c][p] channels-first
__device__ float g_hid[P*HD];     // MLP hidden
__device__ float g_wf[C*CG*9];    // normalized fwd weights  [g][ci][tap][co]
__device__ float g_wb[C*CG*9];    // transposed+flipped      [g][ci'][tap'][co']
__device__ float g_sum4[G*P];     // per-group per-pixel channel sums of g_h

__device__ __forceinline__ float gelu_exact(float v){
    return 0.5f * v * (1.0f + erff(v * 0.70710678118654752f));
}

// ---------------- weight prep: |w| L1-normalized per out-channel ----------
__global__ void prep_w_kernel(const float* __restrict__ wn){
    int o = blockIdx.x;          // 0..95
    int lane = threadIdx.x;      // 0..31
    float s = 0.f;
    for (int i = lane; i < 216; i += 32) s += fabsf(wn[o*216 + i]);
    #pragma unroll
    for (int off = 16; off; off >>= 1) s += __shfl_xor_sync(0xffffffffu, s, off);
    float inv = 1.0f / (s + EPSF);
    int g = o / 24, oo = o % 24;
    for (int i = lane; i < 216; i += 32){
        int ci = i / 9, t = i % 9;
        float v = fabsf(wn[o*216 + i]) * inv;
        // forward conv smem layout: [g][ci][tap][co]
        g_wf[g*5184 + (ci*9 + t)*24 + oo] = v;
        // transpose conv as conv: out-chan=ci, in-chan=oo, tap flipped
        g_wb[g*5184 + (oo*9 + (8 - t))*24 + ci] = v;
    }
}

// ---- LN1 (channels-first) + relu + channel-normalize; init h, sums ------
__global__ void ln1_kernel(const float* __restrict__ x,
                           const float* __restrict__ lw,
                           const float* __restrict__ lb){
    int p = blockIdx.x*256 + threadIdx.x;
    if (p >= P) return;
    int n = p / HW, hw = p % HW;
    const float* xb = x + n*C*HW + hw;
    float s1 = 0.f, s2 = 0.f;
    for (int c = 0; c < C; c++){ float v = xb[c*HW]; s1 += v; s2 += v*v; }
    float u = s1 * (1.0f/96.0f);
    float var = s2 * (1.0f/96.0f) - u*u;
    float rs = rsqrtf(var + 1e-6f);
    float sr = 0.f;
    for (int c = 0; c < C; c++){
        float v = (xb[c*HW] - u) * rs * lw[c] + lb[c];
        sr += fmaxf(v, 0.f);
    }
    float inv = 1.0f / (sr + EPSF);
    float* ob = g_xnn + n*C*HW + hw;
    float* hb = g_h   + n*C*HW + hw;
    for (int c = 0; c < C; c++){
        float v = (xb[c*HW] - u) * rs * lw[c] + lb[c];
        ob[c*HW] = fmaxf(v, 0.f) * inv;
        hb[c*HW] = 1.0f / 96.0f;
    }
    #pragma unroll
    for (int g = 0; g < 4; g++) g_sum4[g*P + p] = 0.25f;  // total = 1
}

// ---------------- grouped 3x3 conv, tile = 4 rows x 56 cols ---------------
// MODE 0: transpose-conv of (normalized-on-load) h; epilogue ratio -> g_t
// MODE 1: forward conv of ratio; epilogue h *= acc, per-group sums -> g_sum4
template<int MODE>
__global__ __launch_bounds__(224) void conv_kernel(){
    extern __shared__ float sm[];
    float* s_in = sm;            // 24 * 6 * 58 = 8352
    float* s_w  = sm + 8352;     // 24 * 9 * 24 = 5184
    const int tid = threadIdx.x;
    const int r0 = blockIdx.x * 4;
    const int g  = blockIdx.y;
    const int n  = blockIdx.z;
    const float* __restrict__ w  = (MODE == 0) ? g_wb : g_wf;
    const float* __restrict__ in = (MODE == 0) ? g_h  : g_t;

    for (int i = tid; i < 5184; i += 224) s_w[i] = w[g*5184 + i];

    const int cb = n*96 + g*24;
    const int pbase = n*HW;
    for (int i = tid; i < 8352; i += 224){
        int ci  = i / 348;
        int rem = i - ci*348;
        int r   = rem / 58;
        int col = rem - r*58 - 1;
        int grow = r0 - 1 + r;
        float v = 0.f;
        if ((unsigned)grow < 56u && (unsigned)col < 56u){
            int pix = grow*56 + col;
            v = in[(cb + ci)*HW + pix];
            if (MODE == 0){
                int q = pbase + pix;
                float s = g_sum4[q] + g_sum4[P+q] + g_sum4[2*P+q] + g_sum4[3*P+q];
                v = v / (s + EPSF);
            }
        }
        s_in[i] = v;
    }
    __syncthreads();

    const int tx = tid % 56;
    const int ty = tid / 56;
    float acc[24];
    #pragma unroll
    for (int i = 0; i < 24; i++) acc[i] = 0.f;

    for (int ci = 0; ci < 24; ci++){
        const float* si = s_in + ci*348 + ty*58 + tx;
        #pragma unroll
        for (int t = 0; t < 9; t++){
            float v = si[(t/3)*58 + (t%3)];
            const float4* wp = (const float4*)(s_w + (ci*9 + t)*24);
            #pragma unroll
            for (int q = 0; q < 6; q++){
                float4 w4 = wp[q];
                acc[4*q+0] += v * w4.x;
                acc[4*q+1] += v * w4.y;
                acc[4*q+2] += v * w4.z;
                acc[4*q+3] += v * w4.w;
            }
        }
    }

    const int pix = (r0 + ty)*56 + tx;
    if (MODE == 0){
        #pragma unroll
        for (int co = 0; co < 24; co++){
            int idx = (cb + co)*HW + pix;
            g_t[idx] = g_xnn[idx] / (acc[co] + EPSF);
        }
    } else {
        float s = 0.f;
        #pragma unroll
        for (int co = 0; co < 24; co++){
            int idx = (cb + co)*HW + pix;
            float hv = g_h[idx] * acc[co];
            g_h[idx] = hv;
            s += hv;
        }
        g_sum4[g*P + pbase + pix] = s;
    }
}

// ---------------- x2 = x + h_normalized --------------------------------
__global__ void residual_kernel(const float* __restrict__ x){
    int idx = blockIdx.x*256 + threadIdx.x;
    int n  = idx / (C*HW);
    int hw = idx % HW;
    int p = n*HW + hw;
    float s = g_sum4[p] + g_sum4[P+p] + g_sum4[2*P+p] + g_sum4[3*P+p];
    g_t[idx] = x[idx] + g_h[idx] / (s + EPSF);
}

// ---------------- LN2 (over channels), write channels-first [c][p] ------
__global__ void ln2_kernel(const float* __restrict__ lw,
                           const float* __restrict__ lb){
    int p = blockIdx.x*256 + threadIdx.x;
    if (p >= P) return;
    int n = p / HW, hw = p % HW;
    const float* xb = g_t + n*C*HW + hw;
    float s1 = 0.f, s2 = 0.f;
    for (int c = 0; c < C; c++){ float v = xb[c*HW]; s1 += v; s2 += v*v; }
    float u = s1 * (1.0f/96.0f);
    float var = s2 * (1.0f/96.0f) - u*u;
    float rs = rsqrtf(var + 1e-5f);
    for (int c = 0; c < C; c++)
        g_lncf[c*P + p] = (xb[c*HW] - u) * rs * lw[c] + lb[c];
}

// ---------------- GEMM1: [P,96] x [96,384] -> gelu -> g_hid --------------
__global__ __launch_bounds__(256) void gemm1_kernel(const float* __restrict__ w1,
                                                    const float* __restrict__ b1){
    __shared__ float As[96*68];
    __shared__ float Bs[96*32];
    const int tid = threadIdx.x;
    const int p0 = blockIdx.x * 64;
    const int n0 = blockIdx.y * 32;
    for (int i = tid; i < 6144; i += 256){
        int c = i >> 6, m = i & 63;
        As[c*68 + m] = g_lncf[c*P + p0 + m];
    }
    for (int i = tid; i < 3072; i += 256){
        int c = i >> 5, j = i & 31;
        Bs[c*32 + j] = w1[c*384 + n0 + j];
    }
    __syncthreads();
    const int tm = tid >> 4, tn = tid & 15;
    float acc[4][2] = {};
    #pragma unroll 4
    for (int k = 0; k < 96; k++){
        float4 a = *(const float4*)(As + k*68 + tm*4);
        float2 b = *(const float2*)(Bs + k*32 + tn*2);
        acc[0][0] += a.x*b.x; acc[0][1] += a.x*b.y;
        acc[1][0] += a.y*b.x; acc[1][1] += a.y*b.y;
        acc[2][0] += a.z*b.x; acc[2][1] += a.z*b.y;
        acc[3][0] += a.w*b.x; acc[3][1] += a.w*b.y;
    }
    int m = p0 + tm*4;
    int j = n0 + tn*2;
    float bj0 = b1[j], bj1 = b1[j+1];
    #pragma unroll
    for (int ii = 0; ii < 4; ii++){
        g_hid[(m+ii)*384 + j]     = gelu_exact(acc[ii][0] + bj0);
        g_hid[(m+ii)*384 + j + 1] = gelu_exact(acc[ii][1] + bj1);
    }
}

// ---- GEMM2: [P,384] x [384,96] + b2 + residual -> out (NCHW) -----------
__global__ __launch_bounds__(256) void gemm2_kernel(const float* __restrict__ w2,
                                                    const float* __restrict__ b2,
                                                    float* __restrict__ out){
    __shared__ float As[32*68];
    __shared__ float Bs[32*96];
    const int tid = threadIdx.x;
    const int p0 = blockIdx.x * 64;       // 3136 % 64 == 0: never straddles images
    const int nimg = p0 / HW;
    const int hw0  = p0 % HW;
    const int tm = tid >> 4, tn = tid & 15;
    float acc[4][6] = {};
    for (int kb = 0; kb < 12; kb++){
        for (int i = tid; i < 2048; i += 256){
            int m = i >> 5, k = i & 31;
            As[k*68 + m] = g_hid[(p0 + m)*384 + kb*32 + k];
        }
        for (int i = tid; i < 3072; i += 256){
            int k = i / 96, c = i - k*96;
            Bs[k*96 + c] = w2[(kb*32 + k)*96 + c];
        }
        __syncthreads();
        #pragma unroll 4
        for (int k = 0; k < 32; k++){
            float4 a = *(const float4*)(As + k*68 + tm*4);
            const float* bp = Bs + k*96 + tn*6;
            float2 b0 = *(const float2*)(bp);
            float2 b1v = *(const float2*)(bp + 2);
            float2 b2v = *(const float2*)(bp + 4);
            float av[4] = {a.x, a.y, a.z, a.w};
            float bv[6] = {b0.x, b0.y, b1v.x, b1v.y, b2v.x, b2v.y};
            #pragma unroll
            for (int ii = 0; ii < 4; ii++)
                #pragma unroll
                for (int jj = 0; jj < 6; jj++)
                    acc[ii][jj] += av[ii] * bv[jj];
        }
        __syncthreads();
    }
    const int cbase = tn*6;
    #pragma unroll
    for (int jj = 0; jj < 6; jj++){
        int c = cbase + jj;
        float bc = b2[c];
        #pragma unroll
        for (int ii = 0; ii < 4; ii++){
            int hw = hw0 + tm*4 + ii;
            int gi = (nimg*96 + c)*HW + hw;
            out[gi] = acc[ii][jj] + bc + g_t[gi];
        }
    }
}

// ---------------- launch ----------------
extern "C" void kernel_launch(void* const* d_in, const int* in_sizes, int n_in,
                              void* d_out, int out_size){
    const float* x    = (const float*)d_in[0];
    const float* ln1w = (const float*)d_in[1];
    const float* ln1b = (const float*)d_in[2];
    const float* wn   = (const float*)d_in[3];
    const float* ln2w = (const float*)d_in[4];
    const float* ln2b = (const float*)d_in[5];
    const float* w1   = (const float*)d_in[6];
    const float* b1   = (const float*)d_in[7];
    const float* w2   = (const float*)d_in[8];
    const float* b2   = (const float*)d_in[9];
    float* out = (float*)d_out;

    const int CONV_SMEM = (8352 + 5184) * 4;   // 54144 B > 48K: opt-in
    cudaFuncSetAttribute(conv_kernel<0>, cudaFuncAttributeMaxDynamicSharedMemorySize, CONV_SMEM);
    cudaFuncSetAttribute(conv_kernel<1>, cudaFuncAttributeMaxDynamicSharedMemorySize, CONV_SMEM);

    prep_w_kernel<<<96, 32>>>(wn);
    ln1_kernel<<<98, 256>>>(x, ln1w, ln1b);

    dim3 cgrid(14, 4, 8);
    for (int it = 0; it < 25; ++it){
        conv_kernel<0><<<cgrid, 224, CONV_SMEM>>>();   // recon -> ratio (fused)
        conv_kernel<1><<<cgrid, 224, CONV_SMEM>>>();   // h update + sums (fused)
    }

    residual_kernel<<<NCHW/256, 256>>>(x);
    ln2_kernel<<<98, 256>>>(ln2w, ln2b);
    gemm1_kernel<<<dim3(392, 12), 256>>>(w1, b1);
    gemm2_kernel<<<392, 256>>>(w2, b2, out);
}

// round 2
// speedup vs baseline: 1.0326x; 1.0326x over previous
#include <cuda_runtime.h>
#include <math.h>

#define NB 8
#define C 96
#define G 4
#define CG 24
#define HH 56
#define HW 3136
#define P 25088            // NB*HW
#define HD 384
#define NCHW (NB*C*HW)     // 2408448
#define EPSF 1e-12f

typedef unsigned long long ull;

__device__ __forceinline__ ull fma2(ull a, ull b, ull c){
    ull d; asm("fma.rn.f32x2 %0, %1, %2, %3;" : "=l"(d) : "l"(a), "l"(b), "l"(c));
    return d;
}
__device__ __forceinline__ ull dup2(float v){
    ull d; asm("mov.b64 %0, {%1, %1};" : "=l"(d) : "f"(v));
    return d;
}
__device__ __forceinline__ void unpack2(ull a, float& lo, float& hi){
    asm("mov.b64 {%0, %1}, %2;" : "=f"(lo), "=f"(hi) : "l"(a));
}

// ---------------- device scratch (no allocations allowed) ----------------
__device__ float g_xnn[NCHW];     // relu(LN1(x)) channel-normalized
__device__ float g_h[NCHW];       // NNMF h (unnormalized; normalized on read)
__device__ float g_t[NCHW];       // ratio buffer, later x2 = x + attn
__device__ float g_lncf[NCHW];    // LN2 output, [c][p] channels-first
__device__ float g_hid[P*HD];     // MLP hidden
__device__ float g_wf[C*CG*9];    // normalized fwd weights  [g][ci][tap][co]
__device__ float g_wb[C*CG*9];    // transposed+flipped      [g][ci'][tap'][co']
__device__ float g_sum4[G*P];     // per-group per-pixel channel sums of g_h

__device__ __forceinline__ float gelu_exact(float v){
    return 0.5f * v * (1.0f + erff(v * 0.70710678118654752f));
}

// ---------------- weight prep: |w| L1-normalized per out-channel ----------
__global__ void prep_w_kernel(const float* __restrict__ wn){
    int o = blockIdx.x;          // 0..95
    int lane = threadIdx.x;      // 0..31
    float s = 0.f;
    for (int i = lane; i < 216; i += 32) s += fabsf(wn[o*216 + i]);
    #pragma unroll
    for (int off = 16; off; off >>= 1) s += __shfl_xor_sync(0xffffffffu, s, off);
    float inv = 1.0f / (s + EPSF);
    int g = o / 24, oo = o % 24;
    for (int i = lane; i < 216; i += 32){
        int ci = i / 9, t = i % 9;
        float v = fabsf(wn[o*216 + i]) * inv;
        g_wf[g*5184 + (ci*9 + t)*24 + oo] = v;
        g_wb[g*5184 + (oo*9 + (8 - t))*24 + ci] = v;
    }
}

// ---- LN1 (channels-first) + relu + channel-normalize; init h, sums ------
__global__ void ln1_kernel(const float* __restrict__ x,
                           const float* __restrict__ lw,
                           const float* __restrict__ lb){
    int p = blockIdx.x*256 + threadIdx.x;
    if (p >= P) return;
    int n = p / HW, hw = p % HW;
    const float* xb = x + n*C*HW + hw;
    float s1 = 0.f, s2 = 0.f;
    for (int c = 0; c < C; c++){ float v = xb[c*HW]; s1 += v; s2 += v*v; }
    float u = s1 * (1.0f/96.0f);
    float var = s2 * (1.0f/96.0f) - u*u;
    float rs = rsqrtf(var + 1e-6f);
    float sr = 0.f;
    for (int c = 0; c < C; c++){
        float v = (xb[c*HW] - u) * rs * lw[c] + lb[c];
        sr += fmaxf(v, 0.f);
    }
    float inv = 1.0f / (sr + EPSF);
    float* ob = g_xnn + n*C*HW + hw;
    float* hb = g_h   + n*C*HW + hw;
    for (int c = 0; c < C; c++){
        float v = (xb[c*HW] - u) * rs * lw[c] + lb[c];
        ob[c*HW] = fmaxf(v, 0.f) * inv;
        hb[c*HW] = 1.0f / 96.0f;
    }
    #pragma unroll
    for (int g = 0; g < 4; g++) g_sum4[g*P + p] = 0.25f;  // total = 1
}

// ---------------- grouped 3x3 conv, tile = 4 rows x 56 cols ---------------
// MODE 0: transpose-conv of (normalized-on-load) h; epilogue ratio -> g_t
// MODE 1: forward conv of ratio; epilogue h *= acc, per-group sums -> g_sum4
// Inner loop uses packed fma.rn.f32x2 over output-channel pairs; weights are
// contiguous in co so LDS.128 delivers two packed multiplier pairs directly.
template<int MODE>
__global__ __launch_bounds__(224, 3) void conv_kernel(){
    extern __shared__ float sm[];
    float* s_in = sm;            // 24 * 6 * 58 = 8352
    float* s_w  = sm + 8352;     // 24 * 9 * 24 = 5184
    const int tid = threadIdx.x;
    const int r0 = blockIdx.x * 4;
    const int g  = blockIdx.y;
    const int n  = blockIdx.z;
    const float* __restrict__ w  = (MODE == 0) ? g_wb : g_wf;
    const float* __restrict__ in = (MODE == 0) ? g_h  : g_t;

    for (int i = tid; i < 5184; i += 224) s_w[i] = w[g*5184 + i];

    const int cb = n*96 + g*24;
    const int pbase = n*HW;
    for (int i = tid; i < 8352; i += 224){
        int ci  = i / 348;
        int rem = i - ci*348;
        int r   = rem / 58;
        int col = rem - r*58 - 1;
        int grow = r0 - 1 + r;
        float v = 0.f;
        if ((unsigned)grow < 56u && (unsigned)col < 56u){
            int pix = grow*56 + col;
            v = in[(cb + ci)*HW + pix];
            if (MODE == 0){
                int q = pbase + pix;
                float s = g_sum4[q] + g_sum4[P+q] + g_sum4[2*P+q] + g_sum4[3*P+q];
                v = v / (s + EPSF);
            }
        }
        s_in[i] = v;
    }
    __syncthreads();

    const int tx = tid % 56;
    const int ty = tid / 56;
    ull acc[12];
    #pragma unroll
    for (int i = 0; i < 12; i++) acc[i] = 0ULL;

    #pragma unroll 2
    for (int ci = 0; ci < 24; ci++){
        const float* si = s_in + ci*348 + ty*58 + tx;
        #pragma unroll
        for (int t = 0; t < 9; t++){
            ull vv = dup2(si[(t/3)*58 + (t%3)]);
            const ulonglong2* wp = (const ulonglong2*)(s_w + (ci*9 + t)*24);
            #pragma unroll
            for (int q = 0; q < 6; q++){
                ulonglong2 wv = wp[q];
                acc[2*q]   = fma2(vv, wv.x, acc[2*q]);
                acc[2*q+1] = fma2(vv, wv.y, acc[2*q+1]);
            }
        }
    }

    float accf[24];
    #pragma unroll
    for (int i = 0; i < 12; i++) unpack2(acc[i], accf[2*i], accf[2*i+1]);

    const int pix = (r0 + ty)*56 + tx;
    if (MODE == 0){
        #pragma unroll
        for (int co = 0; co < 24; co++){
            int idx = (cb + co)*HW + pix;
            g_t[idx] = g_xnn[idx] / (accf[co] + EPSF);
        }
    } else {
        float s = 0.f;
        #pragma unroll
        for (int co = 0; co < 24; co++){
            int idx = (cb + co)*HW + pix;
            float hv = g_h[idx] * accf[co];
            g_h[idx] = hv;
            s += hv;
        }
        g_sum4[g*P + pbase + pix] = s;
    }
}

// ---------------- x2 = x + h_normalized --------------------------------
__global__ void residual_kernel(const float* __restrict__ x){
    int idx = blockIdx.x*256 + threadIdx.x;
    int n  = idx / (C*HW);
    int hw = idx % HW;
    int p = n*HW + hw;
    float s = g_sum4[p] + g_sum4[P+p] + g_sum4[2*P+p] + g_sum4[3*P+p];
    g_t[idx] = x[idx] + g_h[idx] / (s + EPSF);
}

// ---------------- LN2 (over channels), write channels-first [c][p] ------
__global__ void ln2_kernel(const float* __restrict__ lw,
                           const float* __restrict__ lb){
    int p = blockIdx.x*256 + threadIdx.x;
    if (p >= P) return;
    int n = p / HW, hw = p % HW;
    const float* xb = g_t + n*C*HW + hw;
    float s1 = 0.f, s2 = 0.f;
    for (int c = 0; c < C; c++){ float v = xb[c*HW]; s1 += v; s2 += v*v; }
    float u = s1 * (1.0f/96.0f);
    float var = s2 * (1.0f/96.0f) - u*u;
    float rs = rsqrtf(var + 1e-5f);
    for (int c = 0; c < C; c++)
        g_lncf[c*P + p] = (xb[c*HW] - u) * rs * lw[c] + lb[c];
}

// ---------------- GEMM1: [P,96] x [96,384] -> gelu -> g_hid --------------
__global__ __launch_bounds__(256) void gemm1_kernel(const float* __restrict__ w1,
                                                    const float* __restrict__ b1){
    __shared__ float As[96*68];
    __shared__ float Bs[96*32];
    const int tid = threadIdx.x;
    const int p0 = blockIdx.x * 64;
    const int n0 = blockIdx.y * 32;
    for (int i = tid; i < 6144; i += 256){
        int c = i >> 6, m = i & 63;
        As[c*68 + m] = g_lncf[c*P + p0 + m];
    }
    for (int i = tid; i < 3072; i += 256){
        int c = i >> 5, j = i & 31;
        Bs[c*32 + j] = w1[c*384 + n0 + j];
    }
    __syncthreads();
    const int tm = tid >> 4, tn = tid & 15;
    ull acc[4];   // acc[ii] packs (j, j+1)
    #pragma unroll
    for (int i = 0; i < 4; i++) acc[i] = 0ULL;
    #pragma unroll 4
    for (int k = 0; k < 96; k++){
        float4 a = *(const float4*)(As + k*68 + tm*4);
        ull b = *(const ull*)(Bs + k*32 + tn*2);   // 8B aligned
        acc[0] = fma2(dup2(a.x), b, acc[0]);
        acc[1] = fma2(dup2(a.y), b, acc[1]);
        acc[2] = fma2(dup2(a.z), b, acc[2]);
        acc[3] = fma2(dup2(a.w), b, acc[3]);
    }
    int m = p0 + tm*4;
    int j = n0 + tn*2;
    float bj0 = b1[j], bj1 = b1[j+1];
    #pragma unroll
    for (int ii = 0; ii < 4; ii++){
        float a0, a1; unpack2(acc[ii], a0, a1);
        g_hid[(m+ii)*384 + j]     = gelu_exact(a0 + bj0);
        g_hid[(m+ii)*384 + j + 1] = gelu_exact(a1 + bj1);
    }
}

// ---- GEMM2: [P,384] x [384,96] + b2 + residual -> out (NCHW) -----------
__global__ __launch_bounds__(256) void gemm2_kernel(const float* __restrict__ w2,
                                                    const float* __restrict__ b2,
                                                    float* __restrict__ out){
    __shared__ float As[32*68];
    __shared__ float Bs[32*96];
    const int tid = threadIdx.x;
    const int p0 = blockIdx.x * 64;       // 3136 % 64 == 0: never straddles images
    const int nimg = p0 / HW;
    const int hw0  = p0 % HW;
    const int tm = tid >> 4, tn = tid & 15;
    ull acc[4][3];   // acc[ii][jp] packs jj pair (2*jp, 2*jp+1)
    #pragma unroll
    for (int ii = 0; ii < 4; ii++)
        #pragma unroll
        for (int jp = 0; jp < 3; jp++) acc[ii][jp] = 0ULL;
    for (int kb = 0; kb < 12; kb++){
        for (int i = tid; i < 2048; i += 256){
            int m = i >> 5, k = i & 31;
            As[k*68 + m] = g_hid[(p0 + m)*384 + kb*32 + k];
        }
        for (int i = tid; i < 3072; i += 256){
            int k = i / 96, c = i - k*96;
            Bs[k*96 + c] = w2[(kb*32 + k)*96 + c];
        }
        __syncthreads();
        #pragma unroll 4
        for (int k = 0; k < 32; k++){
            float4 a = *(const float4*)(As + k*68 + tm*4);
            const float* bp = Bs + k*96 + tn*6;    // 24B offset: 8B aligned
            ull b0 = *(const ull*)(bp);
            ull b1v = *(const ull*)(bp + 2);
            ull b2v = *(const ull*)(bp + 4);
            ull a0 = dup2(a.x), a1 = dup2(a.y), a2 = dup2(a.z), a3 = dup2(a.w);
            acc[0][0] = fma2(a0, b0, acc[0][0]);
            acc[0][1] = fma2(a0, b1v, acc[0][1]);
            acc[0][2] = fma2(a0, b2v, acc[0][2]);
            acc[1][0] = fma2(a1, b0, acc[1][0]);
            acc[1][1] = fma2(a1, b1v, acc[1][1]);
            acc[1][2] = fma2(a1, b2v, acc[1][2]);
            acc[2][0] = fma2(a2, b0, acc[2][0]);
            acc[2][1] = fma2(a2, b1v, acc[2][1]);
            acc[2][2] = fma2(a2, b2v, acc[2][2]);
            acc[3][0] = fma2(a3, b0, acc[3][0]);
            acc[3][1] = fma2(a3, b1v, acc[3][1]);
            acc[3][2] = fma2(a3, b2v, acc[3][2]);
        }
        __syncthreads();
    }
    const int cbase = tn*6;
    #pragma unroll
    for (int jp = 0; jp < 3; jp++){
        int c0 = cbase + 2*jp;
        float bc0 = b2[c0], bc1 = b2[c0+1];
        #pragma unroll
        for (int ii = 0; ii < 4; ii++){
            float v0, v1; unpack2(acc[ii][jp], v0, v1);
            int hw = hw0 + tm*4 + ii;
            int gi0 = (nimg*96 + c0)*HW + hw;
            int gi1 = (nimg*96 + c0 + 1)*HW + hw;
            out[gi0] = v0 + bc0 + g_t[gi0];
            out[gi1] = v1 + bc1 + g_t[gi1];
        }
    }
}

// ---------------- launch ----------------
extern "C" void kernel_launch(void* const* d_in, const int* in_sizes, int n_in,
                              void* d_out, int out_size){
    const float* x    = (const float*)d_in[0];
    const float* ln1w = (const float*)d_in[1];
    const float* ln1b = (const float*)d_in[2];
    const float* wn   = (const float*)d_in[3];
    const float* ln2w = (const float*)d_in[4];
    const float* ln2b = (const float*)d_in[5];
    const float* w1   = (const float*)d_in[6];
    const float* b1   = (const float*)d_in[7];
    const float* w2   = (const float*)d_in[8];
    const float* b2   = (const float*)d_in[9];
    float* out = (float*)d_out;

    const int CONV_SMEM = (8352 + 5184) * 4;   // 54144 B > 48K: opt-in
    cudaFuncSetAttribute(conv_kernel<0>, cudaFuncAttributeMaxDynamicSharedMemorySize, CONV_SMEM);
    cudaFuncSetAttribute(conv_kernel<1>, cudaFuncAttributeMaxDynamicSharedMemorySize, CONV_SMEM);

    prep_w_kernel<<<96, 32>>>(wn);
    ln1_kernel<<<98, 256>>>(x, ln1w, ln1b);

    dim3 cgrid(14, 4, 8);
    for (int it = 0; it < 25; ++it){
        conv_kernel<0><<<cgrid, 224, CONV_SMEM>>>();   // recon -> ratio (fused)
        conv_kernel<1><<<cgrid, 224, CONV_SMEM>>>();   // h update + sums (fused)
    }

    residual_kernel<<<NCHW/256, 256>>>(x);
    ln2_kernel<<<98, 256>>>(ln2w, ln2b);
    gemm1_kernel<<<dim3(392, 12), 256>>>(w1, b1);
    gemm2_kernel<<<392, 256>>>(w2, b2, out);
}